// round 16
// baseline (speedup 1.0000x reference)
#include <cuda_runtime.h>
#include <cuda_fp16.h>
#include <math.h>

#define NB 4
#define NP 2048
#define NC 128
#define ND 384
#define NH 6
#define FD 192
#define M3 (3*NP)
#define QOFF (NB*ND*M3)

__device__ __half g_normxh[NB*NC*3*NP];
__device__ __half g_qkvh[3*NB*ND*3*NP];
__device__ __half g_aoh[NB*ND*3*NP];
__device__ __half g_Gh[NB*NP*1536];
__device__ __half g_x5h[NB*2*NC*3*NP];
__device__ float  g_vnx[NB*NC*3*NP];
__device__ __half g_nx2h[NB*NC*3*NP];
__device__ float  g_p3[NB*2*NC*3*NP];
__device__ float  g_d3[NB*2*NC*3*NP];
__device__ __half g_hh[NB*2*NC*3*NP];
__device__ float  g_p4[NB*NC*3*NP];
__device__ float  g_d4[NB*NC*3*NP];
__device__ __half g_cwh[512*128];
__device__ __half g_wrh[360448];

__device__ __forceinline__ float fexp2(float x) {
    float r;
    asm("ex2.approx.f32 %0, %1;" : "=f"(r) : "f"(x));
    return r;
}
__device__ __forceinline__ void mma16(float* d, const unsigned* a, unsigned b0, unsigned b1) {
    asm volatile("mma.sync.aligned.m16n8k16.row.col.f32.f16.f16.f32 "
                 "{%0,%1,%2,%3},{%4,%5,%6,%7},{%8,%9},{%0,%1,%2,%3};"
                 : "+f"(d[0]), "+f"(d[1]), "+f"(d[2]), "+f"(d[3])
                 : "r"(a[0]), "r"(a[1]), "r"(a[2]), "r"(a[3]), "r"(b0), "r"(b1));
}
__device__ __forceinline__ void ldmx4(unsigned* r, unsigned addr) {
    asm volatile("ldmatrix.sync.aligned.m8n8.x4.shared.b16 {%0,%1,%2,%3}, [%4];"
                 : "=r"(r[0]), "=r"(r[1]), "=r"(r[2]), "=r"(r[3]) : "r"(addr));
}
__device__ __forceinline__ void ldmx4t(unsigned* r, unsigned addr) {
    asm volatile("ldmatrix.sync.aligned.m8n8.x4.trans.shared.b16 {%0,%1,%2,%3}, [%4];"
                 : "=r"(r[0]), "=r"(r[1]), "=r"(r[2]), "=r"(r[3]) : "r"(addr));
}
__device__ __forceinline__ void ldmx2(unsigned* r, unsigned addr) {
    asm volatile("ldmatrix.sync.aligned.m8n8.x2.shared.b16 {%0,%1}, [%2];"
                 : "=r"(r[0]), "=r"(r[1]) : "r"(addr));
}
__device__ __forceinline__ void cpa16(unsigned dst, const void* src) {
    asm volatile("cp.async.cg.shared.global [%0], [%1], 16;" :: "r"(dst), "l"(src));
}
__device__ __forceinline__ void cpac() { asm volatile("cp.async.commit_group;"); }
__device__ __forceinline__ void cpaw1() { asm volatile("cp.async.wait_group 1;"); }

// k16-fragment order decode (32-k chunks)
__device__ __forceinline__ void frag16_decode(int j, int Cin, int& o, int& k) {
    int per_tile = Cin << 7;
    int tile = j / per_tile;
    int rem = j - tile * per_tile;
    int chunk = rem >> 12;
    int r2 = rem & 4095;
    int frag = r2 >> 8;
    int within = r2 & 255;
    int lane = within >> 3, h = within & 7;
    int wy = frag >> 2, kf = (frag >> 1) & 1, mf = frag & 1;
    int r = (lane >> 2) + ((h >> 1) & 1) * 8;
    int c = ((lane & 3) << 1) + (h & 1) + ((h >> 2) << 3);
    o = (tile << 7) + (wy << 5) + (mf << 4) + r;
    k = (chunk << 5) + (kf << 4) + c;
}

__global__ void prep_w(const float* __restrict__ Wq, const float* __restrict__ Wk,
                       const float* __restrict__ Wv, const float* __restrict__ Wo,
                       const float* __restrict__ W2, const float* __restrict__ W3,
                       const float* __restrict__ U3, const float* __restrict__ W4,
                       const float* __restrict__ U4, __half* __restrict__ wr)
{
    int i = blockIdx.x*256 + threadIdx.x;
    if (i >= 360448) return;
    const float* src;
    int j, Cin;
    if      (i < 49152)  { src = Wq; j = i;          Cin = 128; }
    else if (i < 98304)  { src = Wk; j = i - 49152;  Cin = 128; }
    else if (i < 147456) { src = Wv; j = i - 98304;  Cin = 128; }
    else if (i < 196608) { src = Wo; j = i - 147456; Cin = 384; }
    else if (i < 229376) { src = W2; j = i - 196608; Cin = 256; }
    else if (i < 262144) { src = W3; j = i - 229376; Cin = 128; }
    else if (i < 294912) { src = U3; j = i - 262144; Cin = 128; }
    else if (i < 327680) { src = W4; j = i - 294912; Cin = 256; }
    else                 { src = U4; j = i - 327680; Cin = 256; }
    int o, k;
    frag16_decode(j, Cin, o, k);
    wr[i] = __float2half_rn(src[o*Cin + k]);
}

__global__ void prep_cw(const float* __restrict__ W1, const float* __restrict__ U1,
                        __half* __restrict__ CW)
{
    int idx = blockIdx.x * 256 + threadIdx.x;
    if (idx >= 512*128) return;
    int o, k;
    frag16_decode(idx, 128, o, k);
    int a = o >> 7, oo = o & 127;
    float v;
    if      (a == 0) v = W1[oo*256 + k];
    else if (a == 1) v = W1[oo*256 + 128 + k] - W1[oo*256 + k];
    else if (a == 2) v = U1[oo*256 + k];
    else             v = U1[oo*256 + 128 + k] - U1[oo*256 + k];
    CW[idx] = __float2half_rn(v);
}

// ---------------- vector-norm layernorm (half output) ----------------
__global__ __launch_bounds__(128) void ln_k(const float* __restrict__ in,
                                            const float* __restrict__ g,
                                            const float* __restrict__ bb,
                                            __half* __restrict__ out, int mode)
{
    int bn = blockIdx.x;
    int b = bn >> 11, n = bn & 2047;
    int c = threadIdx.x;
    float v0, v1, v2;
    if (mode == 0) {
        const float* p = in + (long long)bn*384 + 3*c;
        v0 = p[0]; v1 = p[1]; v2 = p[2];
    } else {
        const float* p = in + ((long long)b*NC + c)*M3 + n;
        v0 = p[0]; v1 = p[2048]; v2 = p[4096];
    }
    float nrm = sqrtf(v0*v0 + v1*v1 + v2*v2 + 1e-6f);
    float s = nrm, s2 = nrm*nrm;
    for (int m = 16; m; m >>= 1) {
        s  += __shfl_xor_sync(0xffffffffu, s,  m);
        s2 += __shfl_xor_sync(0xffffffffu, s2, m);
    }
    __shared__ float sb[8];
    int w = c >> 5, lane = c & 31;
    if (!lane) { sb[w] = s; sb[4 + w] = s2; }
    __syncthreads();
    float ts  = sb[0] + sb[1] + sb[2] + sb[3];
    float ts2 = sb[4] + sb[5] + sb[6] + sb[7];
    float mu  = ts * (1.f/128.f);
    float var = ts2 * (1.f/128.f) - mu*mu;
    float nhat = (nrm - mu) / sqrtf(var + 1e-5f);
    float scale = (g[c]*nhat + bb[c]) / nrm;
    __half* q = out + ((long long)b*NC + c)*M3 + n;
    q[0] = __float2half_rn(v0*scale);
    q[2048] = __float2half_rn(v1*scale);
    q[4096] = __float2half_rn(v2*scale);
}

// ---------------- GEMM v7: fp16 m16n8k16, BK=64 ----------------
// stage bytes: W 16384 | X 17408 -> 33792; x3 = 101376
#define GSMEM 101376
__global__ __launch_bounds__(256, 2) void gemm_k(
    const __half* __restrict__ W, const __half* __restrict__ Wb,
    const __half* __restrict__ X, float* __restrict__ Y, float* __restrict__ Y2,
    const float* __restrict__ Res,
    int Cin, int ldx,
    long long xsb, long long xsi, long long ysb, long long ysi,
    int oso, int osm, int zflag, int mode, float oscale, int ysplit)
{
    extern __shared__ char smc[];
    int z = blockIdx.z;
    int b  = (zflag == 1) ? z/3 : z;
    int i3 = (zflag == 1) ? z%3 : 0;
    const __half* xb = X + (long long)b*xsb + (long long)i3*xsi;
    int by = blockIdx.y;
    int o0;
    float* yb;
    float osc = oscale;
    if (zflag == 2) {
        int wsel = by / 3;
        o0 = (by % 3) * 128;
        W += wsel * 49152;
        yb = Y + (long long)wsel*QOFF + (long long)b*ysb;
        if (wsel) osc = 1.0f;
    } else if (ysplit > 0 && by >= ysplit) {
        o0 = (by - ysplit) * 128;
        W = Wb;
        yb = Y2 + (long long)b*ysb + (long long)i3*ysi;
    } else {
        o0 = by * 128;
        yb = Y + (long long)b*ysb + (long long)i3*ysi;
    }
    int m0 = blockIdx.x * 128;
    int tid = threadIdx.x;
    int wid = tid >> 5, lane = tid & 31;
    int a_ = lane >> 2, b_ = lane & 3;
    int wy = wid >> 1, wx = wid & 1;
    unsigned sm_u = (unsigned)__cvta_generic_to_shared(smc);

    float acc[2][8][4];
    #pragma unroll
    for (int i = 0; i < 2; i++)
        #pragma unroll
        for (int j = 0; j < 8; j++)
            #pragma unroll
            for (int c = 0; c < 4; c++) acc[i][j][c] = 0.f;

    int nchunk = Cin >> 6;
    int frow = tid >> 4, fc8 = (tid & 15) << 3;

    #define GFILL(ch) do { \
        int k0 = (ch) << 6; \
        int stg = (ch) % 3; \
        unsigned swu = sm_u + (unsigned)(stg*33792); \
        unsigned sxu = swu + 16384u; \
        const __half* wbase = W + (long long)o0*Cin + ((long long)k0 << 7); \
        cpa16(swu + (unsigned)(tid*16),         wbase + tid*8); \
        cpa16(swu + (unsigned)((tid+256)*16),   wbase + (tid+256)*8); \
        cpa16(swu + (unsigned)((tid+512)*16),   wbase + (tid+512)*8); \
        cpa16(swu + (unsigned)((tid+768)*16),   wbase + (tid+768)*8); \
        cpa16(sxu + (unsigned)((frow*136 + fc8)*2),        xb + (long long)(k0 + frow)*ldx + m0 + fc8); \
        cpa16(sxu + (unsigned)(((frow+16)*136 + fc8)*2),   xb + (long long)(k0 + frow + 16)*ldx + m0 + fc8); \
        cpa16(sxu + (unsigned)(((frow+32)*136 + fc8)*2),   xb + (long long)(k0 + frow + 32)*ldx + m0 + fc8); \
        cpa16(sxu + (unsigned)(((frow+48)*136 + fc8)*2),   xb + (long long)(k0 + frow + 48)*ldx + m0 + fc8); \
    } while (0)

    GFILL(0); cpac();
    if (nchunk > 1) GFILL(1);
    cpac();

    int t4 = lane >> 3, r8 = lane & 7;
    unsigned xoff = (unsigned)((((t4 & 1)*8 + r8)*136 + wx*64 + (t4 >> 1)*8)*2);

    for (int ch = 0; ch < nchunk; ch++) {
        cpaw1();
        __syncthreads();
        int stg = ch % 3;
        unsigned swu = sm_u + (unsigned)(stg*33792);
        unsigned sxu = swu + 16384u;
        const char* swb = smc + stg*33792;
        #pragma unroll
        for (int kf = 0; kf < 4; kf++) {
            int wofs = ((kf >> 1) << 13) + (wy << 11) + ((kf & 1) << 10);
            uint4 a0v = *(const uint4*)(swb + wofs + (lane << 4));
            uint4 a1v = *(const uint4*)(swb + wofs + 512 + (lane << 4));
            #pragma unroll
            for (int nf2 = 0; nf2 < 4; nf2++) {
                unsigned Bv[4];
                ldmx4t(Bv, sxu + xoff + kf*4352u + nf2*32u);
                mma16(acc[0][nf2*2],     (const unsigned*)&a0v, Bv[0], Bv[1]);
                mma16(acc[0][nf2*2 + 1], (const unsigned*)&a0v, Bv[2], Bv[3]);
                mma16(acc[1][nf2*2],     (const unsigned*)&a1v, Bv[0], Bv[1]);
                mma16(acc[1][nf2*2 + 1], (const unsigned*)&a1v, Bv[2], Bv[3]);
            }
        }
        if (ch + 2 < nchunk) GFILL(ch + 2);
        cpac();
    }

    int ob = o0 + wy*32, mb = m0 + wx*64;
    if (osm == 1) {
        #pragma unroll
        for (int mf = 0; mf < 2; mf++)
            #pragma unroll
            for (int nf = 0; nf < 8; nf++) {
                int o = ob + mf*16 + a_;
                int m = mb + nf*8 + 2*b_;
                float2 v0 = make_float2(acc[mf][nf][0], acc[mf][nf][1]);
                float2 v1 = make_float2(acc[mf][nf][2], acc[mf][nf][3]);
                if (mode & 1) {
                    long long rb = (long long)b*NP*ND;
                    v0.x += Res[rb + (long long)(m & 2047)*ND + 3*o + (m >> 11)];
                    v0.y += Res[rb + (long long)((m+1) & 2047)*ND + 3*o + ((m+1) >> 11)];
                    v1.x += Res[rb + (long long)(m & 2047)*ND + 3*(o+8) + (m >> 11)];
                    v1.y += Res[rb + (long long)((m+1) & 2047)*ND + 3*(o+8) + ((m+1) >> 11)];
                }
                if (mode & 4) {
                    long long eo0 = (long long)(yb - Y) + (long long)o*oso + m;
                    long long eo1 = eo0 + (long long)8*oso;
                    __half* Yh = (__half*)Y;
                    *(__half2*)(Yh + eo0) = __floats2half2_rn(v0.x*osc, v0.y*osc);
                    *(__half2*)(Yh + eo1) = __floats2half2_rn(v1.x*osc, v1.y*osc);
                } else {
                    *(float2*)(yb + (long long)o*oso + m) = v0;
                    *(float2*)(yb + (long long)(o+8)*oso + m) = v1;
                }
            }
    } else {
        #pragma unroll
        for (int mf = 0; mf < 2; mf++)
            #pragma unroll
            for (int nf = 0; nf < 8; nf++)
                #pragma unroll
                for (int c = 0; c < 4; c++) {
                    int o = ob + mf*16 + a_ + ((c >> 1) ? 8 : 0);
                    int m = mb + nf*8 + 2*b_ + (c & 1);
                    if (mode & 4) {
                        long long eo = (long long)(yb - Y) + (long long)o*oso + (long long)m*osm;
                        ((__half*)Y)[eo] = __float2half_rn(acc[mf][nf][c]);
                    } else {
                        yb[(long long)o*oso + (long long)m*osm] = acc[mf][nf][c];
                    }
                }
    }
}

// ---------------- flash v9 (R15, unchanged) ----------------
#define QSB 0
#define PSB 52224
#define ALB 70656
#define REDB 71168
#define RED2B 72192
#define KRB 73216
#define VRB 128512
#define FTC_SMEM 183808

__global__ __launch_bounds__(256, 1) void flash_tc(const __half* __restrict__ Q,
                                                   const __half* __restrict__ K,
                                                   const __half* __restrict__ V,
                                                   __half* __restrict__ O)
{
    extern __shared__ char smc[];
    __half* Ps  = (__half*)(smc + PSB);
    float* al_s = (float*)(smc + ALB);
    float* red  = (float*)(smc + REDB);
    float* red2 = (float*)(smc + RED2B);
    unsigned sm_u = (unsigned)__cvta_generic_to_shared(smc);

    int n0 = blockIdx.x * 128;
    long long hb = (long long)(blockIdx.z*NH + blockIdx.y) * FD * NP;
    const __half* Qb = Q + hb;
    const __half* Kb = K + hb;
    const __half* Vb = V + hb;
    __half* Ob = O + hb;

    int tid = threadIdx.x;
    int wid = tid >> 5, lane = tid & 31;
    int a_ = lane >> 2, b_ = lane & 3;
    int qg = wid >> 1, kh = wid & 1;
    int qgb = qg << 5, khb = kh << 5;
    int db = wid * 24;

    #define FKV(t, bi) do { \
        int kt = (t) << 6; \
        unsigned ku = sm_u + (unsigned)(KRB + (bi)*27648); \
        unsigned vu = sm_u + (unsigned)(VRB + (bi)*27648); \
        _Pragma("unroll") \
        for (int i = 0; i < 6; i++) { \
            int idx = tid + i*256; \
            int d = idx >> 3, c = idx & 7; \
            cpa16(ku + (unsigned)(d*144 + c*16), Kb + (long long)d*NP + kt + c*8); \
            cpa16(vu + (unsigned)(d*144 + c*16), Vb + (long long)d*NP + kt + c*8); \
        } \
    } while (0)

    #pragma unroll
    for (int i = 0; i < 12; i++) {
        int idx = tid + i*256;
        int d = idx >> 4, c = idx & 15;
        cpa16(sm_u + (unsigned)(QSB + d*272 + c*16), Qb + (long long)d*NP + n0 + c*8);
    }
    FKV(0, 0); cpac();

    int t4 = lane >> 3, r8 = lane & 7;
    unsigned qa_base = sm_u + (unsigned)(QSB + (((t4 >> 1)*8 + r8)*272) + (qgb + (t4 & 1)*8)*2);
    unsigned kb_lane = (unsigned)((((t4 & 1)*8 + r8)*144) + (khb + (t4 >> 1)*8)*2);
    unsigned pa_lane = sm_u + (unsigned)(PSB + (((t4 & 1)*8 + r8)*144) + ((t4 >> 1)*8)*2);
    unsigned vb_lane = (unsigned)(((db + (t4 >> 1)*8 + r8)*144) + ((t4 & 1)*8)*2);
    unsigned v2_lane = (unsigned)(((db + 16 + r8)*144) + (((lane >> 3) & 1)*8)*2);

    float m_run[4] = {-1e30f, -1e30f, -1e30f, -1e30f};
    float l_run[4] = {0.f, 0.f, 0.f, 0.f};
    float o_acc[8][3][4];
    #pragma unroll
    for (int i = 0; i < 8; i++)
        #pragma unroll
        for (int j = 0; j < 3; j++)
            #pragma unroll
            for (int c = 0; c < 4; c++) o_acc[i][j][c] = 0.f;

    for (int t = 0; t < 32; t++) {
        if (t + 1 < 32) FKV(t + 1, (t + 1) & 1);
        cpac();
        cpaw1();
        __syncthreads();
        int bi = t & 1;
        unsigned kaddr = sm_u + (unsigned)(KRB + bi*27648) + kb_lane;
        unsigned vaddr4 = sm_u + (unsigned)(VRB + bi*27648) + vb_lane;
        unsigned vaddr2 = sm_u + (unsigned)(VRB + bi*27648) + v2_lane;

        float s[2][4][4];
        #pragma unroll
        for (int qf = 0; qf < 2; qf++)
            #pragma unroll
            for (int kg = 0; kg < 4; kg++)
                #pragma unroll
                for (int c = 0; c < 4; c++) s[qf][kg][c] = 0.f;
        #pragma unroll
        for (int kf = 0; kf < 12; kf++) {
            unsigned A0[4], A1[4], Ba[4], Bb[4];
            ldmx4t(A0, qa_base + kf*4352);
            ldmx4t(A1, qa_base + kf*4352 + 32);
            ldmx4t(Ba, kaddr + kf*2304);
            ldmx4t(Bb, kaddr + kf*2304 + 32);
            mma16(s[0][0], A0, Ba[0], Ba[1]);
            mma16(s[0][1], A0, Ba[2], Ba[3]);
            mma16(s[1][0], A1, Ba[0], Ba[1]);
            mma16(s[1][1], A1, Ba[2], Ba[3]);
            mma16(s[0][2], A0, Bb[0], Bb[1]);
            mma16(s[0][3], A0, Bb[2], Bb[3]);
            mma16(s[1][2], A1, Bb[0], Bb[1]);
            mma16(s[1][3], A1, Bb[2], Bb[3]);
        }

        #pragma unroll
        for (int r = 0; r < 4; r++) {
            int qf = r >> 1, hi = (r & 1) << 1;
            float m = fmaxf(fmaxf(s[qf][0][hi], s[qf][0][hi+1]),
                            fmaxf(s[qf][1][hi], s[qf][1][hi+1]));
            m = fmaxf(m, fmaxf(fmaxf(s[qf][2][hi], s[qf][2][hi+1]),
                               fmaxf(s[qf][3][hi], s[qf][3][hi+1])));
            m = fmaxf(m, __shfl_xor_sync(0xffffffffu, m, 1));
            m = fmaxf(m, __shfl_xor_sync(0xffffffffu, m, 2));
            if (b_ == 0)
                red[(qgb + qf*16 + ((r & 1) << 3) + a_)*2 + kh] = m;
        }
        __syncthreads();

        float alpha[4];
        #pragma unroll
        for (int r = 0; r < 4; r++) {
            int row = qgb + (r >> 1)*16 + ((r & 1) << 3) + a_;
            float tm = fmaxf(red[row*2], red[row*2 + 1]);
            float mn = fmaxf(m_run[r], tm);
            alpha[r] = fexp2(m_run[r] - mn);
            m_run[r] = mn;
            if (kh == 0 && b_ == 0) al_s[row] = alpha[r];
        }
        float psum[4] = {0.f, 0.f, 0.f, 0.f};
        #pragma unroll
        for (int qf = 0; qf < 2; qf++)
            #pragma unroll
            for (int c2 = 0; c2 < 2; c2++) {
                int row = qgb + qf*16 + (c2 << 3) + a_;
                float mrow = m_run[qf*2 + c2];
                #pragma unroll
                for (int kg = 0; kg < 4; kg++) {
                    float p0 = fexp2(s[qf][kg][c2*2]     - mrow);
                    float p1 = fexp2(s[qf][kg][c2*2 + 1] - mrow);
                    psum[qf*2 + c2] += p0 + p1;
                    *(__half2*)(Ps + row*72 + khb + kg*8 + 2*b_) = __floats2half2_rn(p0, p1);
                }
            }
        #pragma unroll
        for (int r = 0; r < 4; r++) {
            float ps = psum[r];
            ps += __shfl_xor_sync(0xffffffffu, ps, 1);
            ps += __shfl_xor_sync(0xffffffffu, ps, 2);
            if (b_ == 0)
                red2[(qgb + (r >> 1)*16 + ((r & 1) << 3) + a_)*2 + kh] = ps;
        }
        __syncthreads();

        #pragma unroll
        for (int r = 0; r < 4; r++) {
            int row = qgb + (r >> 1)*16 + ((r & 1) << 3) + a_;
            l_run[r] = l_run[r]*alpha[r] + red2[row*2] + red2[row*2 + 1];
        }

        #pragma unroll
        for (int qb = 0; qb < 8; qb++) {
            float al0 = al_s[qb*16 + a_];
            float al1 = al_s[qb*16 + 8 + a_];
            #pragma unroll
            for (int nd = 0; nd < 3; nd++) {
                o_acc[qb][nd][0] *= al0; o_acc[qb][nd][1] *= al0;
                o_acc[qb][nd][2] *= al1; o_acc[qb][nd][3] *= al1;
            }
        }
        #pragma unroll
        for (int kc = 0; kc < 4; kc++) {
            unsigned Vb4[4], Vb2[2];
            ldmx4(Vb4, vaddr4 + kc*32);
            ldmx2(Vb2, vaddr2 + kc*32);
            #pragma unroll
            for (int qb = 0; qb < 8; qb++) {
                unsigned Pa[4];
                ldmx4(Pa, pa_lane + qb*2304 + kc*32);
                mma16(o_acc[qb][0], Pa, Vb4[0], Vb4[1]);
                mma16(o_acc[qb][1], Pa, Vb4[2], Vb4[3]);
                mma16(o_acc[qb][2], Pa, Vb2[0], Vb2[1]);
            }
        }
        __syncthreads();
    }

    if (kh == 0 && b_ == 0) {
        #pragma unroll
        for (int r = 0; r < 4; r++)
            al_s[qgb + (r >> 1)*16 + ((r & 1) << 3) + a_] = 1.f / l_run[r];
    }
    __syncthreads();
    #pragma unroll
    for (int qb = 0; qb < 8; qb++) {
        float i0 = al_s[qb*16 + a_];
        float i1 = al_s[qb*16 + 8 + a_];
        #pragma unroll
        for (int nd = 0; nd < 3; nd++) {
            int d0 = db + nd*8 + 2*b_;
            long long r0 = (long long)d0*NP + n0 + qb*16 + a_;
            Ob[r0]          = __float2half_rn(o_acc[qb][nd][0] * i0);
            Ob[r0 + NP]     = __float2half_rn(o_acc[qb][nd][1] * i0);
            Ob[r0 + 8]      = __float2half_rn(o_acc[qb][nd][2] * i1);
            Ob[r0 + NP + 8] = __float2half_rn(o_acc[qb][nd][3] * i1);
        }
    }
}

// ---------------- kNN gather + VN-leaky + mean pool (half G) ----------------
__global__ __launch_bounds__(128) void gather_leaky(const __half* __restrict__ G,
                                                    const int* __restrict__ knn,
                                                    __half* __restrict__ X5)
{
    int bn = blockIdx.x;
    int b = bn >> 11, n = bn & 2047;
    int o = threadIdx.x;
    __shared__ int ridx[8];
    if (o < 8) ridx[o] = knn[((b*8 + o) << 11) + n];
    __syncthreads();
    const __half* gc = G + (long long)bn*1536;
    float pc0 = __half2float(gc[128 + o]),        dc0 = __half2float(gc[384 + o]);
    float pc1 = __half2float(gc[512 + 128 + o]),  dc1 = __half2float(gc[512 + 384 + o]);
    float pc2 = __half2float(gc[1024 + 128 + o]), dc2 = __half2float(gc[1024 + 384 + o]);
    float a0 = 0.f, a1 = 0.f, a2 = 0.f;
    #pragma unroll
    for (int k = 0; k < 8; k++) {
        const __half* gr = G + (long long)ridx[k]*1536;
        float p0 = __half2float(gr[o]) + pc0;
        float p1 = __half2float(gr[512 + o]) + pc1;
        float p2 = __half2float(gr[1024 + o]) + pc2;
        float d0 = __half2float(gr[256 + o]) + dc0;
        float d1 = __half2float(gr[512 + 256 + o]) + dc1;
        float d2 = __half2float(gr[1024 + 256 + o]) + dc2;
        float dot = p0*d0 + p1*d1 + p2*d2;
        if (dot < 0.f) {
            float f = 0.8f * dot / (d0*d0 + d1*d1 + d2*d2 + 1e-6f);
            p0 -= f*d0; p1 -= f*d1; p2 -= f*d2;
        }
        a0 += p0; a1 += p1; a2 += p2;
    }
    __half* y = X5 + (long long)b*(2*NC*M3) + (long long)(128 + o)*M3 + n;
    y[0] = __float2half_rn(a0*0.125f);
    y[2048] = __float2half_rn(a1*0.125f);
    y[4096] = __float2half_rn(a2*0.125f);
}

// ---------------- elementwise VN-leaky (half out) ----------------
__global__ void leaky_ew(const float* __restrict__ P, const float* __restrict__ D,
                         __half* __restrict__ Y)
{
    int idx = blockIdx.x*256 + threadIdx.x;
    int n = idx & 2047;
    int bo = idx >> 11;
    long long base = ((long long)bo*3 << 11) + n;
    float p0 = P[base], p1 = P[base + 2048], p2 = P[base + 4096];
    float d0 = D[base], d1 = D[base + 2048], d2 = D[base + 4096];
    float dot = p0*d0 + p1*d1 + p2*d2;
    if (dot < 0.f) {
        float f = 0.8f * dot / (d0*d0 + d1*d1 + d2*d2 + 1e-6f);
        p0 -= f*d0; p1 -= f*d1; p2 -= f*d2;
    }
    Y[base] = __float2half_rn(p0);
    Y[base + 2048] = __float2half_rn(p1);
    Y[base + 4096] = __float2half_rn(p2);
}

// ---------------- conv4 leaky + residual + output transpose ----------------
__global__ void final_k(const float* __restrict__ P, const float* __restrict__ D,
                        const float* __restrict__ vnx, float* __restrict__ out)
{
    int idx = blockIdx.x*256 + threadIdx.x;
    int n = idx & 2047;
    int o = (idx >> 11) & 127;
    int b = idx >> 18;
    long long base2 = (((long long)(b*NC + o))*3 << 11) + n;
    float p0 = P[base2], p1 = P[base2 + 2048], p2 = P[base2 + 4096];
    float d0 = D[base2], d1 = D[base2 + 2048], d2 = D[base2 + 4096];
    float dot = p0*d0 + p1*d1 + p2*d2;
    if (dot < 0.f) {
        float f = 0.8f * dot / (d0*d0 + d1*d1 + d2*d2 + 1e-6f);
        p0 -= f*d0; p1 -= f*d1; p2 -= f*d2;
    }
    float r0 = vnx[base2], r1 = vnx[base2 + 2048], r2 = vnx[base2 + 4096];
    float* q = out + ((long long)(b*NP + n))*ND + 3*o;
    q[0] = r0 + p0; q[1] = r1 + p1; q[2] = r2 + p2;
}

// ---------------- host ----------------
extern "C" void kernel_launch(void* const* d_in, const int* in_sizes, int n_in,
                              void* d_out, int out_size)
{
    (void)in_sizes; (void)n_in; (void)out_size;
    const float* x  = (const float*)d_in[0];
    const int* knn  = (const int*)d_in[1];
    const float* g1 = (const float*)d_in[2];
    const float* b1 = (const float*)d_in[3];
    const float* g2 = (const float*)d_in[4];
    const float* b2 = (const float*)d_in[5];
    const float* Wq = (const float*)d_in[6];
    const float* Wk = (const float*)d_in[7];
    const float* Wv = (const float*)d_in[8];
    const float* Wo = (const float*)d_in[9];
    const float* W1 = (const float*)d_in[10];
    const float* U1 = (const float*)d_in[11];
    const float* W2 = (const float*)d_in[12];
    const float* W3 = (const float*)d_in[13];
    const float* U3 = (const float*)d_in[14];
    const float* W4 = (const float*)d_in[15];
    const float* U4 = (const float*)d_in[16];
    float* out = (float*)d_out;

    float *vnx,*p3,*d3,*p4,*d4;
    __half *normxh,*qh,*aoh,*Gh,*x5h,*nx2h,*hh,*cwh,*wrh;
    cudaGetSymbolAddress((void**)&normxh, g_normxh);
    cudaGetSymbolAddress((void**)&qh, g_qkvh);
    cudaGetSymbolAddress((void**)&aoh, g_aoh);
    cudaGetSymbolAddress((void**)&Gh,  g_Gh);
    cudaGetSymbolAddress((void**)&x5h, g_x5h);
    cudaGetSymbolAddress((void**)&vnx, g_vnx);
    cudaGetSymbolAddress((void**)&nx2h, g_nx2h);
    cudaGetSymbolAddress((void**)&p3, g_p3);
    cudaGetSymbolAddress((void**)&d3, g_d3);
    cudaGetSymbolAddress((void**)&hh,  g_hh);
    cudaGetSymbolAddress((void**)&p4, g_p4);
    cudaGetSymbolAddress((void**)&d4, g_d4);
    cudaGetSymbolAddress((void**)&cwh, g_cwh);
    cudaGetSymbolAddress((void**)&wrh, g_wrh);

    cudaFuncSetAttribute(flash_tc, cudaFuncAttributeMaxDynamicSharedMemorySize, FTC_SMEM);
    cudaFuncSetAttribute(gemm_k, cudaFuncAttributeMaxDynamicSharedMemorySize, GSMEM);

    prep_w<<<1408, 256>>>(Wq, Wk, Wv, Wo, W2, W3, U3, W4, U4, wrh);
    prep_cw<<<256, 256>>>(W1, U1, cwh);
    ln_k<<<NB*NP, 128>>>(x, g1, b1, normxh, 0);

    long long sN = (long long)NC*M3;
    long long sQ = (long long)ND*M3;
    long long sX5 = (long long)2*NC*M3;
    const float qsc = 0.125f * 1.44269504088896f;

    gemm_k<<<dim3(48,9,NB), 256, GSMEM>>>(wrh, nullptr, normxh, (float*)qh, nullptr, nullptr,
                                          128, M3, sN, 0, sQ, 0, M3, 1, 2, 4, qsc, 0);

    flash_tc<<<dim3(16, NH, NB), 256, FTC_SMEM>>>(qh, qh + QOFF, qh + 2*QOFF, aoh);

    gemm_k<<<dim3(48,1,NB), 256, GSMEM>>>(wrh + 147456, nullptr, aoh, (float*)x5h, nullptr, nullptr,
                                          384, M3, sQ, 0, sX5, 0, M3, 1, 0, 4, 1.0f, 0);

    // graph-feature GEMM -> Gh (half)
    gemm_k<<<dim3(16,4,12), 256, GSMEM>>>(cwh, nullptr, normxh, (float*)Gh, nullptr, nullptr,
                                          128, M3, sN, 2048, (long long)NP*1536, 512, 1, 1536, 1, 4, 1.0f, 0);
    gather_leaky<<<NB*NP, 128>>>(Gh, knn, x5h);

    gemm_k<<<dim3(48,1,NB), 256, GSMEM>>>(wrh + 196608, nullptr, x5h, vnx, nullptr, x,
                                          256, M3, sX5, 0, sN, 0, M3, 1, 0, 1, 1.0f, 0);

    ln_k<<<NB*NP, 128>>>(vnx, g2, b2, nx2h, 1);

    gemm_k<<<dim3(48,4,NB), 256, GSMEM>>>(wrh + 229376, wrh + 262144, nx2h, p3, d3, nullptr,
                                          128, M3, sN, 0, sX5, 0, M3, 1, 0, 0, 1.0f, 2);
    leaky_ew<<<NB*2*NC*NP/256, 256>>>(p3, d3, hh);

    gemm_k<<<dim3(48,2,NB), 256, GSMEM>>>(wrh + 294912, wrh + 327680, hh, p4, d4, nullptr,
                                          256, M3, sX5, 0, sN, 0, M3, 1, 0, 0, 1.0f, 1);

    final_k<<<NB*NC*NP/256, 256>>>(p4, d4, vnx, out);
}

// round 17
// speedup vs baseline: 1.0156x; 1.0156x over previous
#include <cuda_runtime.h>
#include <cuda_fp16.h>
#include <math.h>

#define NB 4
#define NP 2048
#define NC 128
#define ND 384
#define NH 6
#define FD 192
#define M3 (3*NP)
#define QOFF (NB*ND*M3)

__device__ __half g_normxh[NB*NC*3*NP];
__device__ __half g_qkvh[3*NB*ND*3*NP];
__device__ __half g_aoh[NB*ND*3*NP];
__device__ float  g_G [NB*NP*1536];
__device__ __half g_x5h[NB*2*NC*3*NP];
__device__ float  g_vnx[NB*NC*3*NP];
__device__ __half g_nx2h[NB*NC*3*NP];
__device__ float  g_p3[NB*2*NC*3*NP];
__device__ float  g_d3[NB*2*NC*3*NP];
__device__ __half g_hh[NB*2*NC*3*NP];
__device__ float  g_p4[NB*NC*3*NP];
__device__ float  g_d4[NB*NC*3*NP];
__device__ __half g_cwh[512*128];
__device__ __half g_wrh[360448];

__device__ __forceinline__ float fexp2(float x) {
    float r;
    asm("ex2.approx.f32 %0, %1;" : "=f"(r) : "f"(x));
    return r;
}
__device__ __forceinline__ void mma16(float* d, const unsigned* a, unsigned b0, unsigned b1) {
    asm volatile("mma.sync.aligned.m16n8k16.row.col.f32.f16.f16.f32 "
                 "{%0,%1,%2,%3},{%4,%5,%6,%7},{%8,%9},{%0,%1,%2,%3};"
                 : "+f"(d[0]), "+f"(d[1]), "+f"(d[2]), "+f"(d[3])
                 : "r"(a[0]), "r"(a[1]), "r"(a[2]), "r"(a[3]), "r"(b0), "r"(b1));
}
__device__ __forceinline__ void ldmx4(unsigned* r, unsigned addr) {
    asm volatile("ldmatrix.sync.aligned.m8n8.x4.shared.b16 {%0,%1,%2,%3}, [%4];"
                 : "=r"(r[0]), "=r"(r[1]), "=r"(r[2]), "=r"(r[3]) : "r"(addr));
}
__device__ __forceinline__ void ldmx4t(unsigned* r, unsigned addr) {
    asm volatile("ldmatrix.sync.aligned.m8n8.x4.trans.shared.b16 {%0,%1,%2,%3}, [%4];"
                 : "=r"(r[0]), "=r"(r[1]), "=r"(r[2]), "=r"(r[3]) : "r"(addr));
}
__device__ __forceinline__ void ldmx2(unsigned* r, unsigned addr) {
    asm volatile("ldmatrix.sync.aligned.m8n8.x2.shared.b16 {%0,%1}, [%2];"
                 : "=r"(r[0]), "=r"(r[1]) : "r"(addr));
}
__device__ __forceinline__ void cpa16(unsigned dst, const void* src) {
    asm volatile("cp.async.cg.shared.global [%0], [%1], 16;" :: "r"(dst), "l"(src));
}
__device__ __forceinline__ void cpac() { asm volatile("cp.async.commit_group;"); }
__device__ __forceinline__ void cpaw1() { asm volatile("cp.async.wait_group 1;"); }

// k16-fragment order decode (32-k chunks)
__device__ __forceinline__ void frag16_decode(int j, int Cin, int& o, int& k) {
    int per_tile = Cin << 7;
    int tile = j / per_tile;
    int rem = j - tile * per_tile;
    int chunk = rem >> 12;
    int r2 = rem & 4095;
    int frag = r2 >> 8;
    int within = r2 & 255;
    int lane = within >> 3, h = within & 7;
    int wy = frag >> 2, kf = (frag >> 1) & 1, mf = frag & 1;
    int r = (lane >> 2) + ((h >> 1) & 1) * 8;
    int c = ((lane & 3) << 1) + (h & 1) + ((h >> 2) << 3);
    o = (tile << 7) + (wy << 5) + (mf << 4) + r;
    k = (chunk << 5) + (kf << 4) + c;
}

__global__ void prep_w(const float* __restrict__ Wq, const float* __restrict__ Wk,
                       const float* __restrict__ Wv, const float* __restrict__ Wo,
                       const float* __restrict__ W2, const float* __restrict__ W3,
                       const float* __restrict__ U3, const float* __restrict__ W4,
                       const float* __restrict__ U4, __half* __restrict__ wr)
{
    int i = blockIdx.x*256 + threadIdx.x;
    if (i >= 360448) return;
    const float* src;
    int j, Cin;
    if      (i < 49152)  { src = Wq; j = i;          Cin = 128; }
    else if (i < 98304)  { src = Wk; j = i - 49152;  Cin = 128; }
    else if (i < 147456) { src = Wv; j = i - 98304;  Cin = 128; }
    else if (i < 196608) { src = Wo; j = i - 147456; Cin = 384; }
    else if (i < 229376) { src = W2; j = i - 196608; Cin = 256; }
    else if (i < 262144) { src = W3; j = i - 229376; Cin = 128; }
    else if (i < 294912) { src = U3; j = i - 262144; Cin = 128; }
    else if (i < 327680) { src = W4; j = i - 294912; Cin = 256; }
    else                 { src = U4; j = i - 327680; Cin = 256; }
    int o, k;
    frag16_decode(j, Cin, o, k);
    wr[i] = __float2half_rn(src[o*Cin + k]);
}

__global__ void prep_cw(const float* __restrict__ W1, const float* __restrict__ U1,
                        __half* __restrict__ CW)
{
    int idx = blockIdx.x * 256 + threadIdx.x;
    if (idx >= 512*128) return;
    int o, k;
    frag16_decode(idx, 128, o, k);
    int a = o >> 7, oo = o & 127;
    float v;
    if      (a == 0) v = W1[oo*256 + k];
    else if (a == 1) v = W1[oo*256 + 128 + k] - W1[oo*256 + k];
    else if (a == 2) v = U1[oo*256 + k];
    else             v = U1[oo*256 + 128 + k] - U1[oo*256 + k];
    CW[idx] = __float2half_rn(v);
}

// ---------------- vector-norm layernorm (half output) ----------------
__global__ __launch_bounds__(128) void ln_k(const float* __restrict__ in,
                                            const float* __restrict__ g,
                                            const float* __restrict__ bb,
                                            __half* __restrict__ out, int mode)
{
    int bn = blockIdx.x;
    int b = bn >> 11, n = bn & 2047;
    int c = threadIdx.x;
    float v0, v1, v2;
    if (mode == 0) {
        const float* p = in + (long long)bn*384 + 3*c;
        v0 = p[0]; v1 = p[1]; v2 = p[2];
    } else {
        const float* p = in + ((long long)b*NC + c)*M3 + n;
        v0 = p[0]; v1 = p[2048]; v2 = p[4096];
    }
    float nrm = sqrtf(v0*v0 + v1*v1 + v2*v2 + 1e-6f);
    float s = nrm, s2 = nrm*nrm;
    for (int m = 16; m; m >>= 1) {
        s  += __shfl_xor_sync(0xffffffffu, s,  m);
        s2 += __shfl_xor_sync(0xffffffffu, s2, m);
    }
    __shared__ float sb[8];
    int w = c >> 5, lane = c & 31;
    if (!lane) { sb[w] = s; sb[4 + w] = s2; }
    __syncthreads();
    float ts  = sb[0] + sb[1] + sb[2] + sb[3];
    float ts2 = sb[4] + sb[5] + sb[6] + sb[7];
    float mu  = ts * (1.f/128.f);
    float var = ts2 * (1.f/128.f) - mu*mu;
    float nhat = (nrm - mu) / sqrtf(var + 1e-5f);
    float scale = (g[c]*nhat + bb[c]) / nrm;
    __half* q = out + ((long long)b*NC + c)*M3 + n;
    q[0] = __float2half_rn(v0*scale);
    q[2048] = __float2half_rn(v1*scale);
    q[4096] = __float2half_rn(v2*scale);
}

// ---------------- GEMM v7: fp16 m16n8k16, BK=64 ----------------
// stage bytes: W 16384 | X 17408 -> 33792; x3 = 101376
#define GSMEM 101376
__global__ __launch_bounds__(256, 2) void gemm_k(
    const __half* __restrict__ W, const __half* __restrict__ Wb,
    const __half* __restrict__ X, float* __restrict__ Y, float* __restrict__ Y2,
    const float* __restrict__ Res,
    int Cin, int ldx,
    long long xsb, long long xsi, long long ysb, long long ysi,
    int oso, int osm, int zflag, int mode, float oscale, int ysplit)
{
    extern __shared__ char smc[];
    int z = blockIdx.z;
    int b  = (zflag == 1) ? z/3 : z;
    int i3 = (zflag == 1) ? z%3 : 0;
    const __half* xb = X + (long long)b*xsb + (long long)i3*xsi;
    int by = blockIdx.y;
    int o0;
    float* yb;
    float osc = oscale;
    if (zflag == 2) {
        int wsel = by / 3;
        o0 = (by % 3) * 128;
        W += wsel * 49152;
        yb = Y + (long long)wsel*QOFF + (long long)b*ysb;
        if (wsel) osc = 1.0f;
    } else if (ysplit > 0 && by >= ysplit) {
        o0 = (by - ysplit) * 128;
        W = Wb;
        yb = Y2 + (long long)b*ysb + (long long)i3*ysi;
    } else {
        o0 = by * 128;
        yb = Y + (long long)b*ysb + (long long)i3*ysi;
    }
    int m0 = blockIdx.x * 128;
    int tid = threadIdx.x;
    int wid = tid >> 5, lane = tid & 31;
    int a_ = lane >> 2, b_ = lane & 3;
    int wy = wid >> 1, wx = wid & 1;
    unsigned sm_u = (unsigned)__cvta_generic_to_shared(smc);

    float acc[2][8][4];
    #pragma unroll
    for (int i = 0; i < 2; i++)
        #pragma unroll
        for (int j = 0; j < 8; j++)
            #pragma unroll
            for (int c = 0; c < 4; c++) acc[i][j][c] = 0.f;

    int nchunk = Cin >> 6;
    int frow = tid >> 4, fc8 = (tid & 15) << 3;

    #define GFILL(ch) do { \
        int k0 = (ch) << 6; \
        int stg = (ch) % 3; \
        unsigned swu = sm_u + (unsigned)(stg*33792); \
        unsigned sxu = swu + 16384u; \
        const __half* wbase = W + (long long)o0*Cin + ((long long)k0 << 7); \
        cpa16(swu + (unsigned)(tid*16),         wbase + tid*8); \
        cpa16(swu + (unsigned)((tid+256)*16),   wbase + (tid+256)*8); \
        cpa16(swu + (unsigned)((tid+512)*16),   wbase + (tid+512)*8); \
        cpa16(swu + (unsigned)((tid+768)*16),   wbase + (tid+768)*8); \
        cpa16(sxu + (unsigned)((frow*136 + fc8)*2),        xb + (long long)(k0 + frow)*ldx + m0 + fc8); \
        cpa16(sxu + (unsigned)(((frow+16)*136 + fc8)*2),   xb + (long long)(k0 + frow + 16)*ldx + m0 + fc8); \
        cpa16(sxu + (unsigned)(((frow+32)*136 + fc8)*2),   xb + (long long)(k0 + frow + 32)*ldx + m0 + fc8); \
        cpa16(sxu + (unsigned)(((frow+48)*136 + fc8)*2),   xb + (long long)(k0 + frow + 48)*ldx + m0 + fc8); \
    } while (0)

    GFILL(0); cpac();
    if (nchunk > 1) GFILL(1);
    cpac();

    int t4 = lane >> 3, r8 = lane & 7;
    unsigned xoff = (unsigned)((((t4 & 1)*8 + r8)*136 + wx*64 + (t4 >> 1)*8)*2);

    for (int ch = 0; ch < nchunk; ch++) {
        cpaw1();
        __syncthreads();
        int stg = ch % 3;
        unsigned swu = sm_u + (unsigned)(stg*33792);
        unsigned sxu = swu + 16384u;
        const char* swb = smc + stg*33792;
        #pragma unroll
        for (int kf = 0; kf < 4; kf++) {
            int wofs = ((kf >> 1) << 13) + (wy << 11) + ((kf & 1) << 10);
            uint4 a0v = *(const uint4*)(swb + wofs + (lane << 4));
            uint4 a1v = *(const uint4*)(swb + wofs + 512 + (lane << 4));
            #pragma unroll
            for (int nf2 = 0; nf2 < 4; nf2++) {
                unsigned Bv[4];
                ldmx4t(Bv, sxu + xoff + kf*4352u + nf2*32u);
                mma16(acc[0][nf2*2],     (const unsigned*)&a0v, Bv[0], Bv[1]);
                mma16(acc[0][nf2*2 + 1], (const unsigned*)&a0v, Bv[2], Bv[3]);
                mma16(acc[1][nf2*2],     (const unsigned*)&a1v, Bv[0], Bv[1]);
                mma16(acc[1][nf2*2 + 1], (const unsigned*)&a1v, Bv[2], Bv[3]);
            }
        }
        if (ch + 2 < nchunk) GFILL(ch + 2);
        cpac();
    }

    int ob = o0 + wy*32, mb = m0 + wx*64;
    if (osm == 1) {
        #pragma unroll
        for (int mf = 0; mf < 2; mf++)
            #pragma unroll
            for (int nf = 0; nf < 8; nf++) {
                int o = ob + mf*16 + a_;
                int m = mb + nf*8 + 2*b_;
                float2 v0 = make_float2(acc[mf][nf][0], acc[mf][nf][1]);
                float2 v1 = make_float2(acc[mf][nf][2], acc[mf][nf][3]);
                if (mode & 1) {
                    long long rb = (long long)b*NP*ND;
                    v0.x += Res[rb + (long long)(m & 2047)*ND + 3*o + (m >> 11)];
                    v0.y += Res[rb + (long long)((m+1) & 2047)*ND + 3*o + ((m+1) >> 11)];
                    v1.x += Res[rb + (long long)(m & 2047)*ND + 3*(o+8) + (m >> 11)];
                    v1.y += Res[rb + (long long)((m+1) & 2047)*ND + 3*(o+8) + ((m+1) >> 11)];
                }
                if (mode & 4) {
                    long long eo0 = (long long)(yb - Y) + (long long)o*oso + m;
                    long long eo1 = eo0 + (long long)8*oso;
                    __half* Yh = (__half*)Y;
                    *(__half2*)(Yh + eo0) = __floats2half2_rn(v0.x*osc, v0.y*osc);
                    *(__half2*)(Yh + eo1) = __floats2half2_rn(v1.x*osc, v1.y*osc);
                } else {
                    *(float2*)(yb + (long long)o*oso + m) = v0;
                    *(float2*)(yb + (long long)(o+8)*oso + m) = v1;
                }
            }
    } else {
        #pragma unroll
        for (int mf = 0; mf < 2; mf++)
            #pragma unroll
            for (int nf = 0; nf < 8; nf++)
                #pragma unroll
                for (int c = 0; c < 4; c++) {
                    int o = ob + mf*16 + a_ + ((c >> 1) ? 8 : 0);
                    int m = mb + nf*8 + 2*b_ + (c & 1);
                    yb[(long long)o*oso + (long long)m*osm] = acc[mf][nf][c];
                }
    }
}

// ---------------- flash v9 (R15, unchanged) ----------------
#define QSB 0
#define PSB 52224
#define ALB 70656
#define REDB 71168
#define RED2B 72192
#define KRB 73216
#define VRB 128512
#define FTC_SMEM 183808

__global__ __launch_bounds__(256, 1) void flash_tc(const __half* __restrict__ Q,
                                                   const __half* __restrict__ K,
                                                   const __half* __restrict__ V,
                                                   __half* __restrict__ O)
{
    extern __shared__ char smc[];
    __half* Ps  = (__half*)(smc + PSB);
    float* al_s = (float*)(smc + ALB);
    float* red  = (float*)(smc + REDB);
    float* red2 = (float*)(smc + RED2B);
    unsigned sm_u = (unsigned)__cvta_generic_to_shared(smc);

    int n0 = blockIdx.x * 128;
    long long hb = (long long)(blockIdx.z*NH + blockIdx.y) * FD * NP;
    const __half* Qb = Q + hb;
    const __half* Kb = K + hb;
    const __half* Vb = V + hb;
    __half* Ob = O + hb;

    int tid = threadIdx.x;
    int wid = tid >> 5, lane = tid & 31;
    int a_ = lane >> 2, b_ = lane & 3;
    int qg = wid >> 1, kh = wid & 1;
    int qgb = qg << 5, khb = kh << 5;
    int db = wid * 24;

    #define FKV(t, bi) do { \
        int kt = (t) << 6; \
        unsigned ku = sm_u + (unsigned)(KRB + (bi)*27648); \
        unsigned vu = sm_u + (unsigned)(VRB + (bi)*27648); \
        _Pragma("unroll") \
        for (int i = 0; i < 6; i++) { \
            int idx = tid + i*256; \
            int d = idx >> 3, c = idx & 7; \
            cpa16(ku + (unsigned)(d*144 + c*16), Kb + (long long)d*NP + kt + c*8); \
            cpa16(vu + (unsigned)(d*144 + c*16), Vb + (long long)d*NP + kt + c*8); \
        } \
    } while (0)

    #pragma unroll
    for (int i = 0; i < 12; i++) {
        int idx = tid + i*256;
        int d = idx >> 4, c = idx & 15;
        cpa16(sm_u + (unsigned)(QSB + d*272 + c*16), Qb + (long long)d*NP + n0 + c*8);
    }
    FKV(0, 0); cpac();

    int t4 = lane >> 3, r8 = lane & 7;
    unsigned qa_base = sm_u + (unsigned)(QSB + (((t4 >> 1)*8 + r8)*272) + (qgb + (t4 & 1)*8)*2);
    unsigned kb_lane = (unsigned)((((t4 & 1)*8 + r8)*144) + (khb + (t4 >> 1)*8)*2);
    unsigned pa_lane = sm_u + (unsigned)(PSB + (((t4 & 1)*8 + r8)*144) + ((t4 >> 1)*8)*2);
    unsigned vb_lane = (unsigned)(((db + (t4 >> 1)*8 + r8)*144) + ((t4 & 1)*8)*2);
    unsigned v2_lane = (unsigned)(((db + 16 + r8)*144) + (((lane >> 3) & 1)*8)*2);

    float m_run[4] = {-1e30f, -1e30f, -1e30f, -1e30f};
    float l_run[4] = {0.f, 0.f, 0.f, 0.f};
    float o_acc[8][3][4];
    #pragma unroll
    for (int i = 0; i < 8; i++)
        #pragma unroll
        for (int j = 0; j < 3; j++)
            #pragma unroll
            for (int c = 0; c < 4; c++) o_acc[i][j][c] = 0.f;

    for (int t = 0; t < 32; t++) {
        if (t + 1 < 32) FKV(t + 1, (t + 1) & 1);
        cpac();
        cpaw1();
        __syncthreads();
        int bi = t & 1;
        unsigned kaddr = sm_u + (unsigned)(KRB + bi*27648) + kb_lane;
        unsigned vaddr4 = sm_u + (unsigned)(VRB + bi*27648) + vb_lane;
        unsigned vaddr2 = sm_u + (unsigned)(VRB + bi*27648) + v2_lane;

        float s[2][4][4];
        #pragma unroll
        for (int qf = 0; qf < 2; qf++)
            #pragma unroll
            for (int kg = 0; kg < 4; kg++)
                #pragma unroll
                for (int c = 0; c < 4; c++) s[qf][kg][c] = 0.f;
        #pragma unroll
        for (int kf = 0; kf < 12; kf++) {
            unsigned A0[4], A1[4], Ba[4], Bb[4];
            ldmx4t(A0, qa_base + kf*4352);
            ldmx4t(A1, qa_base + kf*4352 + 32);
            ldmx4t(Ba, kaddr + kf*2304);
            ldmx4t(Bb, kaddr + kf*2304 + 32);
            mma16(s[0][0], A0, Ba[0], Ba[1]);
            mma16(s[0][1], A0, Ba[2], Ba[3]);
            mma16(s[1][0], A1, Ba[0], Ba[1]);
            mma16(s[1][1], A1, Ba[2], Ba[3]);
            mma16(s[0][2], A0, Bb[0], Bb[1]);
            mma16(s[0][3], A0, Bb[2], Bb[3]);
            mma16(s[1][2], A1, Bb[0], Bb[1]);
            mma16(s[1][3], A1, Bb[2], Bb[3]);
        }

        #pragma unroll
        for (int r = 0; r < 4; r++) {
            int qf = r >> 1, hi = (r & 1) << 1;
            float m = fmaxf(fmaxf(s[qf][0][hi], s[qf][0][hi+1]),
                            fmaxf(s[qf][1][hi], s[qf][1][hi+1]));
            m = fmaxf(m, fmaxf(fmaxf(s[qf][2][hi], s[qf][2][hi+1]),
                               fmaxf(s[qf][3][hi], s[qf][3][hi+1])));
            m = fmaxf(m, __shfl_xor_sync(0xffffffffu, m, 1));
            m = fmaxf(m, __shfl_xor_sync(0xffffffffu, m, 2));
            if (b_ == 0)
                red[(qgb + qf*16 + ((r & 1) << 3) + a_)*2 + kh] = m;
        }
        __syncthreads();

        float alpha[4];
        #pragma unroll
        for (int r = 0; r < 4; r++) {
            int row = qgb + (r >> 1)*16 + ((r & 1) << 3) + a_;
            float tm = fmaxf(red[row*2], red[row*2 + 1]);
            float mn = fmaxf(m_run[r], tm);
            alpha[r] = fexp2(m_run[r] - mn);
            m_run[r] = mn;
            if (kh == 0 && b_ == 0) al_s[row] = alpha[r];
        }
        float psum[4] = {0.f, 0.f, 0.f, 0.f};
        #pragma unroll
        for (int qf = 0; qf < 2; qf++)
            #pragma unroll
            for (int c2 = 0; c2 < 2; c2++) {
                int row = qgb + qf*16 + (c2 << 3) + a_;
                float mrow = m_run[qf*2 + c2];
                #pragma unroll
                for (int kg = 0; kg < 4; kg++) {
                    float p0 = fexp2(s[qf][kg][c2*2]     - mrow);
                    float p1 = fexp2(s[qf][kg][c2*2 + 1] - mrow);
                    psum[qf*2 + c2] += p0 + p1;
                    *(__half2*)(Ps + row*72 + khb + kg*8 + 2*b_) = __floats2half2_rn(p0, p1);
                }
            }
        #pragma unroll
        for (int r = 0; r < 4; r++) {
            float ps = psum[r];
            ps += __shfl_xor_sync(0xffffffffu, ps, 1);
            ps += __shfl_xor_sync(0xffffffffu, ps, 2);
            if (b_ == 0)
                red2[(qgb + (r >> 1)*16 + ((r & 1) << 3) + a_)*2 + kh] = ps;
        }
        __syncthreads();

        #pragma unroll
        for (int r = 0; r < 4; r++) {
            int row = qgb + (r >> 1)*16 + ((r & 1) << 3) + a_;
            l_run[r] = l_run[r]*alpha[r] + red2[row*2] + red2[row*2 + 1];
        }

        #pragma unroll
        for (int qb = 0; qb < 8; qb++) {
            float al0 = al_s[qb*16 + a_];
            float al1 = al_s[qb*16 + 8 + a_];
            #pragma unroll
            for (int nd = 0; nd < 3; nd++) {
                o_acc[qb][nd][0] *= al0; o_acc[qb][nd][1] *= al0;
                o_acc[qb][nd][2] *= al1; o_acc[qb][nd][3] *= al1;
            }
        }
        #pragma unroll
        for (int kc = 0; kc < 4; kc++) {
            unsigned Vb4[4], Vb2[2];
            ldmx4(Vb4, vaddr4 + kc*32);
            ldmx2(Vb2, vaddr2 + kc*32);
            #pragma unroll
            for (int qb = 0; qb < 8; qb++) {
                unsigned Pa[4];
                ldmx4(Pa, pa_lane + qb*2304 + kc*32);
                mma16(o_acc[qb][0], Pa, Vb4[0], Vb4[1]);
                mma16(o_acc[qb][1], Pa, Vb4[2], Vb4[3]);
                mma16(o_acc[qb][2], Pa, Vb2[0], Vb2[1]);
            }
        }
        __syncthreads();
    }

    if (kh == 0 && b_ == 0) {
        #pragma unroll
        for (int r = 0; r < 4; r++)
            al_s[qgb + (r >> 1)*16 + ((r & 1) << 3) + a_] = 1.f / l_run[r];
    }
    __syncthreads();
    #pragma unroll
    for (int qb = 0; qb < 8; qb++) {
        float i0 = al_s[qb*16 + a_];
        float i1 = al_s[qb*16 + 8 + a_];
        #pragma unroll
        for (int nd = 0; nd < 3; nd++) {
            int d0 = db + nd*8 + 2*b_;
            long long r0 = (long long)d0*NP + n0 + qb*16 + a_;
            Ob[r0]          = __float2half_rn(o_acc[qb][nd][0] * i0);
            Ob[r0 + NP]     = __float2half_rn(o_acc[qb][nd][1] * i0);
            Ob[r0 + 8]      = __float2half_rn(o_acc[qb][nd][2] * i1);
            Ob[r0 + NP + 8] = __float2half_rn(o_acc[qb][nd][3] * i1);
        }
    }
}

// ---------------- kNN gather + VN-leaky + mean pool (float G) ----------------
__global__ __launch_bounds__(128) void gather_leaky(const float* __restrict__ G,
                                                    const int* __restrict__ knn,
                                                    __half* __restrict__ X5)
{
    int bn = blockIdx.x;
    int b = bn >> 11, n = bn & 2047;
    int o = threadIdx.x;
    __shared__ int ridx[8];
    if (o < 8) ridx[o] = knn[((b*8 + o) << 11) + n];
    __syncthreads();
    const float* gc = G + (long long)bn*1536;
    float pc0 = gc[128 + o],        dc0 = gc[384 + o];
    float pc1 = gc[512 + 128 + o],  dc1 = gc[512 + 384 + o];
    float pc2 = gc[1024 + 128 + o], dc2 = gc[1024 + 384 + o];
    float a0 = 0.f, a1 = 0.f, a2 = 0.f;
    #pragma unroll
    for (int k = 0; k < 8; k++) {
        const float* gr = G + (long long)ridx[k]*1536;
        float p0 = gr[o] + pc0;
        float p1 = gr[512 + o] + pc1;
        float p2 = gr[1024 + o] + pc2;
        float d0 = gr[256 + o] + dc0;
        float d1 = gr[512 + 256 + o] + dc1;
        float d2 = gr[1024 + 256 + o] + dc2;
        float dot = p0*d0 + p1*d1 + p2*d2;
        if (dot < 0.f) {
            float f = 0.8f * dot / (d0*d0 + d1*d1 + d2*d2 + 1e-6f);
            p0 -= f*d0; p1 -= f*d1; p2 -= f*d2;
        }
        a0 += p0; a1 += p1; a2 += p2;
    }
    __half* y = X5 + (long long)b*(2*NC*M3) + (long long)(128 + o)*M3 + n;
    y[0] = __float2half_rn(a0*0.125f);
    y[2048] = __float2half_rn(a1*0.125f);
    y[4096] = __float2half_rn(a2*0.125f);
}

// ---------------- elementwise VN-leaky (half out) ----------------
__global__ void leaky_ew(const float* __restrict__ P, const float* __restrict__ D,
                         __half* __restrict__ Y)
{
    int idx = blockIdx.x*256 + threadIdx.x;
    int n = idx & 2047;
    int bo = idx >> 11;
    long long base = ((long long)bo*3 << 11) + n;
    float p0 = P[base], p1 = P[base + 2048], p2 = P[base + 4096];
    float d0 = D[base], d1 = D[base + 2048], d2 = D[base + 4096];
    float dot = p0*d0 + p1*d1 + p2*d2;
    if (dot < 0.f) {
        float f = 0.8f * dot / (d0*d0 + d1*d1 + d2*d2 + 1e-6f);
        p0 -= f*d0; p1 -= f*d1; p2 -= f*d2;
    }
    Y[base] = __float2half_rn(p0);
    Y[base + 2048] = __float2half_rn(p1);
    Y[base + 4096] = __float2half_rn(p2);
}

// ---------------- conv4 leaky + residual + output transpose ----------------
__global__ void final_k(const float* __restrict__ P, const float* __restrict__ D,
                        const float* __restrict__ vnx, float* __restrict__ out)
{
    int idx = blockIdx.x*256 + threadIdx.x;
    int n = idx & 2047;
    int o = (idx >> 11) & 127;
    int b = idx >> 18;
    long long base2 = (((long long)(b*NC + o))*3 << 11) + n;
    float p0 = P[base2], p1 = P[base2 + 2048], p2 = P[base2 + 4096];
    float d0 = D[base2], d1 = D[base2 + 2048], d2 = D[base2 + 4096];
    float dot = p0*d0 + p1*d1 + p2*d2;
    if (dot < 0.f) {
        float f = 0.8f * dot / (d0*d0 + d1*d1 + d2*d2 + 1e-6f);
        p0 -= f*d0; p1 -= f*d1; p2 -= f*d2;
    }
    float r0 = vnx[base2], r1 = vnx[base2 + 2048], r2 = vnx[base2 + 4096];
    float* q = out + ((long long)(b*NP + n))*ND + 3*o;
    q[0] = r0 + p0; q[1] = r1 + p1; q[2] = r2 + p2;
}

// ---------------- host ----------------
extern "C" void kernel_launch(void* const* d_in, const int* in_sizes, int n_in,
                              void* d_out, int out_size)
{
    (void)in_sizes; (void)n_in; (void)out_size;
    const float* x  = (const float*)d_in[0];
    const int* knn  = (const int*)d_in[1];
    const float* g1 = (const float*)d_in[2];
    const float* b1 = (const float*)d_in[3];
    const float* g2 = (const float*)d_in[4];
    const float* b2 = (const float*)d_in[5];
    const float* Wq = (const float*)d_in[6];
    const float* Wk = (const float*)d_in[7];
    const float* Wv = (const float*)d_in[8];
    const float* Wo = (const float*)d_in[9];
    const float* W1 = (const float*)d_in[10];
    const float* U1 = (const float*)d_in[11];
    const float* W2 = (const float*)d_in[12];
    const float* W3 = (const float*)d_in[13];
    const float* U3 = (const float*)d_in[14];
    const float* W4 = (const float*)d_in[15];
    const float* U4 = (const float*)d_in[16];
    float* out = (float*)d_out;

    float *G,*vnx,*p3,*d3,*p4,*d4;
    __half *normxh,*qh,*aoh,*x5h,*nx2h,*hh,*cwh,*wrh;
    cudaGetSymbolAddress((void**)&normxh, g_normxh);
    cudaGetSymbolAddress((void**)&qh, g_qkvh);
    cudaGetSymbolAddress((void**)&aoh, g_aoh);
    cudaGetSymbolAddress((void**)&G,  g_G);
    cudaGetSymbolAddress((void**)&x5h, g_x5h);
    cudaGetSymbolAddress((void**)&vnx, g_vnx);
    cudaGetSymbolAddress((void**)&nx2h, g_nx2h);
    cudaGetSymbolAddress((void**)&p3, g_p3);
    cudaGetSymbolAddress((void**)&d3, g_d3);
    cudaGetSymbolAddress((void**)&hh,  g_hh);
    cudaGetSymbolAddress((void**)&p4, g_p4);
    cudaGetSymbolAddress((void**)&d4, g_d4);
    cudaGetSymbolAddress((void**)&cwh, g_cwh);
    cudaGetSymbolAddress((void**)&wrh, g_wrh);

    cudaFuncSetAttribute(flash_tc, cudaFuncAttributeMaxDynamicSharedMemorySize, FTC_SMEM);
    cudaFuncSetAttribute(gemm_k, cudaFuncAttributeMaxDynamicSharedMemorySize, GSMEM);

    prep_w<<<1408, 256>>>(Wq, Wk, Wv, Wo, W2, W3, U3, W4, U4, wrh);
    prep_cw<<<256, 256>>>(W1, U1, cwh);
    ln_k<<<NB*NP, 128>>>(x, g1, b1, normxh, 0);

    long long sN = (long long)NC*M3;
    long long sQ = (long long)ND*M3;
    long long sX5 = (long long)2*NC*M3;
    const float qsc = 0.125f * 1.44269504088896f;

    gemm_k<<<dim3(48,9,NB), 256, GSMEM>>>(wrh, nullptr, normxh, (float*)qh, nullptr, nullptr,
                                          128, M3, sN, 0, sQ, 0, M3, 1, 2, 4, qsc, 0);

    flash_tc<<<dim3(16, NH, NB), 256, FTC_SMEM>>>(qh, qh + QOFF, qh + 2*QOFF, aoh);

    gemm_k<<<dim3(48,1,NB), 256, GSMEM>>>(wrh + 147456, nullptr, aoh, (float*)x5h, nullptr, nullptr,
                                          384, M3, sQ, 0, sX5, 0, M3, 1, 0, 4, 1.0f, 0);

    // graph-feature GEMM -> G (float, vectorized scatter path)
    gemm_k<<<dim3(16,4,12), 256, GSMEM>>>(cwh, nullptr, normxh, G, nullptr, nullptr,
                                          128, M3, sN, 2048, (long long)NP*1536, 512, 1, 1536, 1, 0, 1.0f, 0);
    gather_leaky<<<NB*NP, 128>>>(G, knn, x5h);

    gemm_k<<<dim3(48,1,NB), 256, GSMEM>>>(wrh + 196608, nullptr, x5h, vnx, nullptr, x,
                                          256, M3, sX5, 0, sN, 0, M3, 1, 0, 1, 1.0f, 0);

    ln_k<<<NB*NP, 128>>>(vnx, g2, b2, nx2h, 1);

    gemm_k<<<dim3(48,4,NB), 256, GSMEM>>>(wrh + 229376, wrh + 262144, nx2h, p3, d3, nullptr,
                                          128, M3, sN, 0, sX5, 0, M3, 1, 0, 0, 1.0f, 2);
    leaky_ew<<<NB*2*NC*NP/256, 256>>>(p3, d3, hh);

    gemm_k<<<dim3(48,2,NB), 256, GSMEM>>>(wrh + 294912, wrh + 327680, hh, p4, d4, nullptr,
                                          256, M3, sX5, 0, sN, 0, M3, 1, 0, 0, 1.0f, 1);

    final_k<<<NB*NC*NP/256, 256>>>(p4, d4, vnx, out);
}